// round 16
// baseline (speedup 1.0000x reference)
#include <cuda_runtime.h>

#define CHN 12
#define CHE 8
#define D 8            // CH_N - CH_N_CONST
#define MSG_IN 34
#define MSG_H 32
#define MSG_OUT 24
#define UPD_IN 28
#define UPD_H 16

#define MAXN 4096
#define MAXB 4

typedef unsigned long long u64;

// Scratch (allocation-free requirement -> __device__ globals)
__device__ __align__(16) float g_agg_a[MAXB * MAXN * D];
__device__ __align__(16) float g_agg_b[MAXB * MAXN * D];
__device__ __align__(16) float g_outdeg[MAXN];
__device__ __align__(16) float g_indeg[MAXN];
// pre arrays in SoA-chunk layout: float4 index ((b*8 + q)*N + n)
__device__ __align__(16) float g_pre_s[MAXB * MAXN * MSG_H];
__device__ __align__(16) float g_pre_t[MAXB * MAXN * MSG_H];

// ---------- packed f32x2 helpers ----------
static __device__ __forceinline__ u64 pk(float a, float b) {
    u64 r;
    asm("mov.b64 %0, {%1, %2};" : "=l"(r) : "f"(a), "f"(b));
    return r;
}
static __device__ __forceinline__ void upk(u64 v, float& a, float& b) {
    asm("mov.b64 {%0, %1}, %2;" : "=f"(a), "=f"(b) : "l"(v));
}
static __device__ __forceinline__ void fma2(u64& acc, u64 w, u64 x) {
    asm("fma.rn.f32x2 %0, %1, %2, %0;" : "+l"(acc) : "l"(w), "l"(x));
}
static __device__ __forceinline__ void red4(float* p, float a, float b, float c, float d) {
    asm volatile("red.global.add.v4.f32 [%0], {%1,%2,%3,%4};"
                 :: "l"(p), "f"(a), "f"(b), "f"(c), "f"(d) : "memory");
}

// ---------- kernel 0: zero scratch ----------
__global__ void k_zero(int B, int N) {
    int i = blockIdx.x * blockDim.x + threadIdx.x;
    int tot = B * N * D;
    if (i < tot) { g_agg_a[i] = 0.0f; g_agg_b[i] = 0.0f; }
    if (i < N)   { g_outdeg[i] = 0.0f; g_indeg[i] = 0.0f; }
}

// ---------- kernel 1: degrees (warp-aggregated on sorted src) ----------
__global__ void k_deg(const int* __restrict__ src, const int* __restrict__ tgt, int E) {
    int e = blockIdx.x * blockDim.x + threadIdx.x;
    int s = -1;
    bool act = e < E;
    if (act) {
        s = src[e];
        atomicAdd(&g_indeg[tgt[e]], 1.0f);   // targets distinct within a warp
    }
    const unsigned FULL = 0xffffffffu;
    int s0 = __shfl_sync(FULL, s, 0);
    bool uni = __all_sync(FULL, s == s0) && (s0 >= 0);
    if (uni) {
        if ((threadIdx.x & 31) == 0) atomicAdd(&g_outdeg[s0], 32.0f);
    } else if (act) {
        atomicAdd(&g_outdeg[s], 1.0f);
    }
}

// ---------- kernel 1.5: per-node layer-1 partial sums (SoA-chunk output) ----------
__global__ void k_pre(const float* __restrict__ nodes,
                      const float* __restrict__ w1, const float* __restrict__ b1,
                      int B, int N) {
    int idx = blockIdx.x * blockDim.x + threadIdx.x;
    if (idx >= B * N) return;
    int b = idx / N, n = idx - b * N;

    float x[CHN];
    const float* np = nodes + ((size_t)b * N + n) * CHN;
#pragma unroll
    for (int c = 0; c < CHN; c++) x[c] = __ldg(np + c);
    float od = __ldg(&g_outdeg[n]);
    float idg = __ldg(&g_indeg[n]);

    float ps[MSG_H], pt[MSG_H];
#pragma unroll 4
    for (int j = 0; j < MSG_H; j++) {
        const float* wr = w1 + j * MSG_IN;
        float a = __ldg(&b1[j]) + __ldg(wr + 32) * od;
        float t = __ldg(wr + 33) * idg;
#pragma unroll
        for (int c = 0; c < CHN; c++) {
            a += __ldg(wr + c) * x[c];
            t += __ldg(wr + 12 + c) * x[c];
        }
        ps[j] = a;
        pt[j] = t;
    }
    float4* os = (float4*)g_pre_s;
    float4* ot = (float4*)g_pre_t;
#pragma unroll
    for (int q = 0; q < 8; q++) {
        os[(size_t)(b * 8 + q) * N + n] = make_float4(ps[4*q], ps[4*q+1], ps[4*q+2], ps[4*q+3]);
        ot[(size_t)(b * 8 + q) * N + n] = make_float4(pt[4*q], pt[4*q+1], pt[4*q+2], pt[4*q+3]);
    }
}

// ---------- kernel 2: per-edge message MLP, adjacent edge pair per thread ----------
__global__ void __launch_bounds__(128, 3)
k_edge(const float* __restrict__ edges,
       const float* __restrict__ w1,
       const float* __restrict__ w2, const float* __restrict__ b2,
       const int* __restrict__ src, const int* __restrict__ tgt,
       float* __restrict__ new_edges, int B, int N, int E) {
    __shared__ __align__(16) u64 sw1e[CHE * 16];   // [f][j2]
    __shared__ __align__(16) u64 sw2[MSG_H * 12];  // [h][o2]
    __shared__ __align__(16) u64 sb2[12];

    const int tid = threadIdx.x;
    for (int i = tid; i < CHE * 16; i += blockDim.x) {
        int f = i >> 4, j2 = i & 15;
        sw1e[i] = pk(w1[(2 * j2) * MSG_IN + 24 + f], w1[(2 * j2 + 1) * MSG_IN + 24 + f]);
    }
    for (int i = tid; i < MSG_H * 12; i += blockDim.x) {
        int h = i / 12, o2 = i - 12 * h;
        sw2[i] = pk(w2[(2 * o2) * MSG_H + h], w2[(2 * o2 + 1) * MSG_H + h]);
    }
    if (tid < 12) sb2[tid] = pk(b2[2 * tid], b2[2 * tid + 1]);
    __syncthreads();

    const int tot = B * E;
    const int g = blockIdx.x * 128 + tid;
    const int i0 = 2 * g, i1 = 2 * g + 1;
    const bool act0 = i0 < tot;
    const bool act1 = i1 < tot;

    int b0 = 0, e0 = 0, s0 = -1, t0 = -1;
    int b1_ = 0, e1 = 0, s1 = -1, t1 = -1;
    if (act0) {
        b0 = i0 >= E ? (i0 >= 2 * E ? (i0 >= 3 * E ? 3 : 2) : 1) : 0;
        e0 = i0 - b0 * E;
        s0 = src[e0]; t0 = tgt[e0];
    }
    if (act1) {
        b1_ = i1 >= E ? (i1 >= 2 * E ? (i1 >= 3 * E ? 3 : 2) : 1) : 0;
        e1 = i1 - b1_ * E;
        s1 = src[e1]; t1 = tgt[e1];
    }
    const bool same_src = act1 && (s1 == s0) && (b1_ == b0);

    // ---- layer-1 node init: h2 = pre_src[s] + pre_tgt[t] ----
    u64 h2a[16], h2b[16];
    {
        const float4* pres = (const float4*)g_pre_s;
        const float4* pret = (const float4*)g_pre_t;
#pragma unroll
        for (int q = 0; q < 8; q++) {
            float4 aS0 = make_float4(0.f, 0.f, 0.f, 0.f);
            float4 aT0 = aS0, aS1 = aS0, aT1 = aS0;
            if (act0) {
                aS0 = __ldg(&pres[(size_t)(b0 * 8 + q) * N + s0]);
                aT0 = __ldg(&pret[(size_t)(b0 * 8 + q) * N + t0]);
            }
            if (act1) {
                aS1 = same_src ? aS0 : __ldg(&pres[(size_t)(b1_ * 8 + q) * N + s1]);
                aT1 = __ldg(&pret[(size_t)(b1_ * 8 + q) * N + t1]);
            }
            h2a[2 * q]     = pk(aS0.x + aT0.x, aS0.y + aT0.y);
            h2a[2 * q + 1] = pk(aS0.z + aT0.z, aS0.w + aT0.w);
            h2b[2 * q]     = pk(aS1.x + aT1.x, aS1.y + aT1.y);
            h2b[2 * q + 1] = pk(aS1.z + aT1.z, aS1.w + aT1.w);
        }
    }

    // ---- layer-1 edge-feature contribution (weights shared across both slots) ----
    {
        float ef0[CHE], ef1[CHE];
#pragma unroll
        for (int c = 0; c < CHE; c++) { ef0[c] = 0.0f; ef1[c] = 0.0f; }
        if (act0) {
            const float4* ep = (const float4*)(edges + ((size_t)b0 * E + e0) * CHE);
            float4 v;
            v = __ldg(ep + 0); ef0[0] = v.x; ef0[1] = v.y; ef0[2] = v.z; ef0[3] = v.w;
            v = __ldg(ep + 1); ef0[4] = v.x; ef0[5] = v.y; ef0[6] = v.z; ef0[7] = v.w;
        }
        if (act1) {
            const float4* ep = (const float4*)(edges + ((size_t)b1_ * E + e1) * CHE);
            float4 v;
            v = __ldg(ep + 0); ef1[0] = v.x; ef1[1] = v.y; ef1[2] = v.z; ef1[3] = v.w;
            v = __ldg(ep + 1); ef1[4] = v.x; ef1[5] = v.y; ef1[6] = v.z; ef1[7] = v.w;
        }
#pragma unroll
        for (int f = 0; f < CHE; f++) {
            u64 x0 = pk(ef0[f], ef0[f]);
            u64 x1 = pk(ef1[f], ef1[f]);
            const ulonglong2* wr = (const ulonglong2*)&sw1e[f * 16];
#pragma unroll
            for (int q = 0; q < 8; q++) {
                ulonglong2 wp = wr[q];
                fma2(h2a[2 * q], wp.x, x0);
                fma2(h2a[2 * q + 1], wp.y, x0);
                fma2(h2b[2 * q], wp.x, x1);
                fma2(h2b[2 * q + 1], wp.y, x1);
            }
        }
    }

    // ---- layer 2 (weights shared across both slots) ----
    u64 m2a[12], m2b[12];
    {
        const ulonglong2* bb = (const ulonglong2*)sb2;
#pragma unroll
        for (int q = 0; q < 6; q++) {
            ulonglong2 bv = bb[q];
            m2a[2 * q] = bv.x; m2a[2 * q + 1] = bv.y;
            m2b[2 * q] = bv.x; m2b[2 * q + 1] = bv.y;
        }
    }
#pragma unroll
    for (int j = 0; j < 16; j++) {
        float h0a, h0b, h1a, h1b;
        upk(h2a[j], h0a, h0b);
        upk(h2b[j], h1a, h1b);
        h0a = fmaxf(h0a, 0.0f); h0b = fmaxf(h0b, 0.0f);
        h1a = fmaxf(h1a, 0.0f); h1b = fmaxf(h1b, 0.0f);
        u64 xa0 = pk(h0a, h0a), xb0 = pk(h0b, h0b);
        u64 xa1 = pk(h1a, h1a), xb1 = pk(h1b, h1b);
        const ulonglong2* wra = (const ulonglong2*)&sw2[(2 * j) * 12];
        const ulonglong2* wrb = (const ulonglong2*)&sw2[(2 * j + 1) * 12];
#pragma unroll
        for (int q = 0; q < 6; q++) {
            ulonglong2 wpa = wra[q];
            ulonglong2 wpb = wrb[q];
            fma2(m2a[2 * q], wpa.x, xa0);
            fma2(m2a[2 * q + 1], wpa.y, xa0);
            fma2(m2a[2 * q], wpb.x, xb0);
            fma2(m2a[2 * q + 1], wpb.y, xb0);
            fma2(m2b[2 * q], wpa.x, xa1);
            fma2(m2b[2 * q + 1], wpa.y, xa1);
            fma2(m2b[2 * q], wpb.x, xb1);
            fma2(m2b[2 * q + 1], wpb.y, xb1);
        }
    }

    // ---- epilogue: edge outputs + m_b scatter (reload edge features; L1 hit) ----
    float ma0[D], ma1[D];
    {
        float m[MSG_OUT];
#pragma unroll
        for (int o = 0; o < 12; o++) upk(m2a[o], m[2 * o], m[2 * o + 1]);
#pragma unroll
        for (int c = 0; c < D; c++) ma0[c] = m[c];
        if (act0) {
            const float4* ep = (const float4*)(edges + ((size_t)b0 * E + e0) * CHE);
            float4 v0 = __ldg(ep + 0), v1 = __ldg(ep + 1);
            float4* op = (float4*)(new_edges + ((size_t)b0 * E + e0) * CHE);
            op[0] = make_float4(
                fminf(fmaxf(v0.x + m[16], -100.0f), 100.0f),
                fminf(fmaxf(v0.y + m[17], -100.0f), 100.0f),
                fminf(fmaxf(v0.z + m[18], -100.0f), 100.0f),
                fminf(fmaxf(v0.w + m[19], -100.0f), 100.0f));
            op[1] = make_float4(
                fminf(fmaxf(v1.x + m[20], -100.0f), 100.0f),
                fminf(fmaxf(v1.y + m[21], -100.0f), 100.0f),
                fminf(fmaxf(v1.z + m[22], -100.0f), 100.0f),
                fminf(fmaxf(v1.w + m[23], -100.0f), 100.0f));
            float* ab = g_agg_b + ((size_t)b0 * N + t0) * D;
            red4(ab,     m[8],  m[9],  m[10], m[11]);
            red4(ab + 4, m[12], m[13], m[14], m[15]);
        }
    }
    {
        float m[MSG_OUT];
#pragma unroll
        for (int o = 0; o < 12; o++) upk(m2b[o], m[2 * o], m[2 * o + 1]);
#pragma unroll
        for (int c = 0; c < D; c++) ma1[c] = m[c];
        if (act1) {
            const float4* ep = (const float4*)(edges + ((size_t)b1_ * E + e1) * CHE);
            float4 v0 = __ldg(ep + 0), v1 = __ldg(ep + 1);
            float4* op = (float4*)(new_edges + ((size_t)b1_ * E + e1) * CHE);
            op[0] = make_float4(
                fminf(fmaxf(v0.x + m[16], -100.0f), 100.0f),
                fminf(fmaxf(v0.y + m[17], -100.0f), 100.0f),
                fminf(fmaxf(v0.z + m[18], -100.0f), 100.0f),
                fminf(fmaxf(v0.w + m[19], -100.0f), 100.0f));
            op[1] = make_float4(
                fminf(fmaxf(v1.x + m[20], -100.0f), 100.0f),
                fminf(fmaxf(v1.y + m[21], -100.0f), 100.0f),
                fminf(fmaxf(v1.z + m[22], -100.0f), 100.0f),
                fminf(fmaxf(v1.w + m[23], -100.0f), 100.0f));
            float* ab = g_agg_b + ((size_t)b1_ * N + t1) * D;
            red4(ab,     m[8],  m[9],  m[10], m[11]);
            red4(ab + 4, m[12], m[13], m[14], m[15]);
        }
    }

    // ---- m_a scatter: combine pair when same source, then warp-uniform reduce ----
    const unsigned FULL = 0xffffffffu;
    const int lane = tid & 31;
    float mc[D];
#pragma unroll
    for (int c = 0; c < D; c++) mc[c] = ma0[c] + (same_src ? ma1[c] : 0.0f);

    int su = __shfl_sync(FULL, s0, 0);
    int bu = __shfl_sync(FULL, b0, 0);
    bool uni = __all_sync(FULL, (s0 == su) && (b0 == bu)) && (su >= 0);
    if (uni) {
        float r[D];
#pragma unroll
        for (int c = 0; c < D; c++) {
            float v = mc[c];
#pragma unroll
            for (int off = 16; off; off >>= 1) v += __shfl_xor_sync(FULL, v, off);
            r[c] = v;
        }
        if (lane == 0) {
            float* aa = g_agg_a + ((size_t)bu * N + su) * D;
            red4(aa,     r[0], r[1], r[2], r[3]);
            red4(aa + 4, r[4], r[5], r[6], r[7]);
        }
        if (act1 && !same_src) {
            float* aa = g_agg_a + ((size_t)b1_ * N + s1) * D;
            red4(aa,     ma1[0], ma1[1], ma1[2], ma1[3]);
            red4(aa + 4, ma1[4], ma1[5], ma1[6], ma1[7]);
        }
    } else {
        if (act0) {
            float* aa = g_agg_a + ((size_t)b0 * N + s0) * D;
            red4(aa,     mc[0], mc[1], mc[2], mc[3]);
            red4(aa + 4, mc[4], mc[5], mc[6], mc[7]);
        }
        if (act1 && !same_src) {
            float* aa = g_agg_a + ((size_t)b1_ * N + s1) * D;
            red4(aa,     ma1[0], ma1[1], ma1[2], ma1[3]);
            red4(aa + 4, ma1[4], ma1[5], ma1[6], ma1[7]);
        }
    }
}

// ---------- kernel 3: per-node update MLP ----------
__global__ void k_node(const float* __restrict__ nodes,
                       const float* __restrict__ w1, const float* __restrict__ b1,
                       const float* __restrict__ w2, const float* __restrict__ b2,
                       float* __restrict__ new_nodes, int B, int N) {
    int idx = blockIdx.x * blockDim.x + threadIdx.x;
    if (idx >= B * N) return;
    int b = idx / N, n = idx - b * N;

    float ux[UPD_IN];
    float od = fmaxf(__ldg(&g_outdeg[n]), 1.0f);
    float idg = fmaxf(__ldg(&g_indeg[n]), 1.0f);
    const float* aa = g_agg_a + ((size_t)b * N + n) * D;
    const float* ab = g_agg_b + ((size_t)b * N + n) * D;
#pragma unroll
    for (int c = 0; c < D; c++) {
        ux[c] = aa[c] / od;
        ux[D + c] = ab[c] / idg;
    }
    const float* np = nodes + ((size_t)b * N + n) * CHN;
#pragma unroll
    for (int c = 0; c < CHN; c++) ux[2 * D + c] = __ldg(np + c);

    float uh[UPD_H];
#pragma unroll
    for (int j = 0; j < UPD_H; j++) {
        float acc = __ldg(&b1[j]);
#pragma unroll
        for (int f = 0; f < UPD_IN; f++) acc += __ldg(&w1[j * UPD_IN + f]) * ux[f];
        uh[j] = fmaxf(acc, 0.0f);
    }

    float* onp = new_nodes + ((size_t)b * N + n) * CHN;
#pragma unroll
    for (int o = 0; o < D; o++) {
        float acc = __ldg(&b2[o]);
#pragma unroll
        for (int j = 0; j < UPD_H; j++) acc += __ldg(&w2[o * UPD_H + j]) * uh[j];
        float v = ux[2 * D + o] + acc;
        onp[o] = fminf(fmaxf(v, -100.0f), 100.0f);
    }
#pragma unroll
    for (int c = D; c < CHN; c++) onp[c] = ux[2 * D + c];
}

extern "C" void kernel_launch(void* const* d_in, const int* in_sizes, int n_in,
                              void* d_out, int out_size) {
    const float* nodes  = (const float*)d_in[0];
    const float* edges  = (const float*)d_in[1];
    const float* msg_w1 = (const float*)d_in[2];
    const float* msg_b1 = (const float*)d_in[3];
    const float* msg_w2 = (const float*)d_in[4];
    const float* msg_b2 = (const float*)d_in[5];
    const float* upd_w1 = (const float*)d_in[6];
    const float* upd_b1 = (const float*)d_in[7];
    const float* upd_w2 = (const float*)d_in[8];
    const float* upd_b2 = (const float*)d_in[9];
    const int* src = (const int*)d_in[10];
    const int* tgt = (const int*)d_in[11];

    const int E = in_sizes[10];
    const int B = in_sizes[1] / (E * CHE);
    const int N = in_sizes[0] / (B * CHN);

    float* out_nodes = (float*)d_out;
    float* out_edges = out_nodes + (size_t)B * N * CHN;

    int zn = B * N * D;
    if (N > zn) zn = N;
    k_zero<<<(zn + 255) / 256, 256>>>(B, N);
    k_deg<<<(E + 255) / 256, 256>>>(src, tgt, E);
    k_pre<<<(B * N + 63) / 64, 64>>>(nodes, msg_w1, msg_b1, B, N);

    int tot = B * E;
    int pairs = (tot + 1) >> 1;
    k_edge<<<(pairs + 127) / 128, 128>>>(edges, msg_w1, msg_w2, msg_b2,
                                         src, tgt, out_edges, B, N, E);

    k_node<<<(B * N + 127) / 128, 128>>>(nodes, upd_w1, upd_b1, upd_w2, upd_b2,
                                         out_nodes, B, N);
    (void)n_in; (void)out_size;
}

// round 17
// speedup vs baseline: 1.0663x; 1.0663x over previous
#include <cuda_runtime.h>

#define CHN 12
#define CHE 8
#define D 8            // CH_N - CH_N_CONST
#define MSG_IN 34
#define MSG_H 32
#define MSG_OUT 24
#define UPD_IN 28
#define UPD_H 16

#define MAXN 4096
#define MAXB 4

typedef unsigned long long u64;

// Scratch (allocation-free requirement -> __device__ globals)
__device__ __align__(16) float g_agg_a[MAXB * MAXN * D];
__device__ __align__(16) float g_agg_b[MAXB * MAXN * D];
__device__ __align__(16) float g_outdeg[MAXN];
__device__ __align__(16) float g_indeg[MAXN];
// pre arrays in SoA-chunk layout: float4 index ((b*8 + q)*N + n)
__device__ __align__(16) float g_pre_s[MAXB * MAXN * MSG_H];
__device__ __align__(16) float g_pre_t[MAXB * MAXN * MSG_H];

// ---------- packed f32x2 helpers ----------
static __device__ __forceinline__ u64 pk(float a, float b) {
    u64 r;
    asm("mov.b64 %0, {%1, %2};" : "=l"(r) : "f"(a), "f"(b));
    return r;
}
static __device__ __forceinline__ void upk(u64 v, float& a, float& b) {
    asm("mov.b64 {%0, %1}, %2;" : "=f"(a), "=f"(b) : "l"(v));
}
static __device__ __forceinline__ void fma2(u64& acc, u64 w, u64 x) {
    asm("fma.rn.f32x2 %0, %1, %2, %0;" : "+l"(acc) : "l"(w), "l"(x));
}
static __device__ __forceinline__ void red4(float* p, float a, float b, float c, float d) {
    asm volatile("red.global.add.v4.f32 [%0], {%1,%2,%3,%4};"
                 :: "l"(p), "f"(a), "f"(b), "f"(c), "f"(d) : "memory");
}

// ---------- kernel 0: zero scratch ----------
__global__ void k_zero(int B, int N) {
    int i = blockIdx.x * blockDim.x + threadIdx.x;
    int tot = B * N * D;
    if (i < tot) { g_agg_a[i] = 0.0f; g_agg_b[i] = 0.0f; }
    if (i < N)   { g_outdeg[i] = 0.0f; g_indeg[i] = 0.0f; }
}

// ---------- kernel 1: degrees (warp-aggregated on sorted src) ----------
__global__ void k_deg(const int* __restrict__ src, const int* __restrict__ tgt, int E) {
    int e = blockIdx.x * blockDim.x + threadIdx.x;
    int s = -1;
    bool act = e < E;
    if (act) {
        s = src[e];
        atomicAdd(&g_indeg[tgt[e]], 1.0f);   // targets distinct within a warp
    }
    const unsigned FULL = 0xffffffffu;
    int s0 = __shfl_sync(FULL, s, 0);
    bool uni = __all_sync(FULL, s == s0) && (s0 >= 0);
    if (uni) {
        if ((threadIdx.x & 31) == 0) atomicAdd(&g_outdeg[s0], 32.0f);
    } else if (act) {
        atomicAdd(&g_outdeg[s], 1.0f);
    }
}

// ---------- kernel 1.5: per-node layer-1 partial sums (SoA-chunk output) ----------
__global__ void k_pre(const float* __restrict__ nodes,
                      const float* __restrict__ w1, const float* __restrict__ b1,
                      int B, int N) {
    int idx = blockIdx.x * blockDim.x + threadIdx.x;
    if (idx >= B * N) return;
    int b = idx / N, n = idx - b * N;

    float x[CHN];
    const float* np = nodes + ((size_t)b * N + n) * CHN;
#pragma unroll
    for (int c = 0; c < CHN; c++) x[c] = __ldg(np + c);
    float od = __ldg(&g_outdeg[n]);
    float idg = __ldg(&g_indeg[n]);

    float ps[MSG_H], pt[MSG_H];
#pragma unroll 4
    for (int j = 0; j < MSG_H; j++) {
        const float* wr = w1 + j * MSG_IN;
        float a = __ldg(&b1[j]) + __ldg(wr + 32) * od;
        float t = __ldg(wr + 33) * idg;
#pragma unroll
        for (int c = 0; c < CHN; c++) {
            a += __ldg(wr + c) * x[c];
            t += __ldg(wr + 12 + c) * x[c];
        }
        ps[j] = a;
        pt[j] = t;
    }
    float4* os = (float4*)g_pre_s;
    float4* ot = (float4*)g_pre_t;
#pragma unroll
    for (int q = 0; q < 8; q++) {
        os[(size_t)(b * 8 + q) * N + n] = make_float4(ps[4*q], ps[4*q+1], ps[4*q+2], ps[4*q+3]);
        ot[(size_t)(b * 8 + q) * N + n] = make_float4(pt[4*q], pt[4*q+1], pt[4*q+2], pt[4*q+3]);
    }
}

// ---------- kernel 2: per-edge message MLP ----------
// Each warp handles 64 consecutive edges: slot0 = base+lane (stride-1 coalesced),
// slot1 = base+lane+32 (stride-1 coalesced, usually same source as slot0).
__global__ void __launch_bounds__(128, 3)
k_edge(const float* __restrict__ edges,
       const float* __restrict__ w1,
       const float* __restrict__ w2, const float* __restrict__ b2,
       const int* __restrict__ src, const int* __restrict__ tgt,
       float* __restrict__ new_edges, int B, int N, int E) {
    __shared__ __align__(16) u64 sw1e[CHE * 16];   // [f][j2]
    __shared__ __align__(16) u64 sw2[MSG_H * 12];  // [h][o2]
    __shared__ __align__(16) u64 sb2[12];

    const int tid = threadIdx.x;
    for (int i = tid; i < CHE * 16; i += blockDim.x) {
        int f = i >> 4, j2 = i & 15;
        sw1e[i] = pk(w1[(2 * j2) * MSG_IN + 24 + f], w1[(2 * j2 + 1) * MSG_IN + 24 + f]);
    }
    for (int i = tid; i < MSG_H * 12; i += blockDim.x) {
        int h = i / 12, o2 = i - 12 * h;
        sw2[i] = pk(w2[(2 * o2) * MSG_H + h], w2[(2 * o2 + 1) * MSG_H + h]);
    }
    if (tid < 12) sb2[tid] = pk(b2[2 * tid], b2[2 * tid + 1]);
    __syncthreads();

    const int tot = B * E;
    const int lane = tid & 31;
    const int i0 = blockIdx.x * 256 + (tid >> 5) * 64 + lane;
    const int i1 = i0 + 32;
    const bool act0 = i0 < tot;
    const bool act1 = i1 < tot;

    int b0 = 0, e0 = 0, s0 = -1, t0 = -1;
    int b1_ = 0, e1 = 0, s1 = -1, t1 = -1;
    if (act0) {
        b0 = i0 >= E ? (i0 >= 2 * E ? (i0 >= 3 * E ? 3 : 2) : 1) : 0;
        e0 = i0 - b0 * E;
        s0 = src[e0]; t0 = tgt[e0];
    }
    if (act1) {
        b1_ = i1 >= E ? (i1 >= 2 * E ? (i1 >= 3 * E ? 3 : 2) : 1) : 0;
        e1 = i1 - b1_ * E;
        s1 = src[e1]; t1 = tgt[e1];
    }
    const bool same_src = act1 && (s1 == s0) && (b1_ == b0);

    // ---- layer-1 node init: h2 = pre_src[s] + pre_tgt[t] ----
    u64 h2a[16], h2b[16];
    {
        const float4* pres = (const float4*)g_pre_s;
        const float4* pret = (const float4*)g_pre_t;
#pragma unroll
        for (int q = 0; q < 8; q++) {
            float4 aS0 = make_float4(0.f, 0.f, 0.f, 0.f);
            float4 aT0 = aS0, aS1 = aS0, aT1 = aS0;
            if (act0) {
                aS0 = __ldg(&pres[(size_t)(b0 * 8 + q) * N + s0]);
                aT0 = __ldg(&pret[(size_t)(b0 * 8 + q) * N + t0]);
            }
            if (act1) {
                aS1 = same_src ? aS0 : __ldg(&pres[(size_t)(b1_ * 8 + q) * N + s1]);
                aT1 = __ldg(&pret[(size_t)(b1_ * 8 + q) * N + t1]);
            }
            h2a[2 * q]     = pk(aS0.x + aT0.x, aS0.y + aT0.y);
            h2a[2 * q + 1] = pk(aS0.z + aT0.z, aS0.w + aT0.w);
            h2b[2 * q]     = pk(aS1.x + aT1.x, aS1.y + aT1.y);
            h2b[2 * q + 1] = pk(aS1.z + aT1.z, aS1.w + aT1.w);
        }
    }

    // ---- layer-1 edge-feature contribution (weights shared across both slots) ----
    {
        float ef0[CHE], ef1[CHE];
#pragma unroll
        for (int c = 0; c < CHE; c++) { ef0[c] = 0.0f; ef1[c] = 0.0f; }
        if (act0) {
            const float4* ep = (const float4*)(edges + ((size_t)b0 * E + e0) * CHE);
            float4 v;
            v = __ldg(ep + 0); ef0[0] = v.x; ef0[1] = v.y; ef0[2] = v.z; ef0[3] = v.w;
            v = __ldg(ep + 1); ef0[4] = v.x; ef0[5] = v.y; ef0[6] = v.z; ef0[7] = v.w;
        }
        if (act1) {
            const float4* ep = (const float4*)(edges + ((size_t)b1_ * E + e1) * CHE);
            float4 v;
            v = __ldg(ep + 0); ef1[0] = v.x; ef1[1] = v.y; ef1[2] = v.z; ef1[3] = v.w;
            v = __ldg(ep + 1); ef1[4] = v.x; ef1[5] = v.y; ef1[6] = v.z; ef1[7] = v.w;
        }
#pragma unroll
        for (int f = 0; f < CHE; f++) {
            u64 x0 = pk(ef0[f], ef0[f]);
            u64 x1 = pk(ef1[f], ef1[f]);
            const ulonglong2* wr = (const ulonglong2*)&sw1e[f * 16];
#pragma unroll
            for (int q = 0; q < 8; q++) {
                ulonglong2 wp = wr[q];
                fma2(h2a[2 * q], wp.x, x0);
                fma2(h2a[2 * q + 1], wp.y, x0);
                fma2(h2b[2 * q], wp.x, x1);
                fma2(h2b[2 * q + 1], wp.y, x1);
            }
        }
    }

    // ---- layer 2 (weights shared across both slots) ----
    u64 m2a[12], m2b[12];
    {
        const ulonglong2* bb = (const ulonglong2*)sb2;
#pragma unroll
        for (int q = 0; q < 6; q++) {
            ulonglong2 bv = bb[q];
            m2a[2 * q] = bv.x; m2a[2 * q + 1] = bv.y;
            m2b[2 * q] = bv.x; m2b[2 * q + 1] = bv.y;
        }
    }
#pragma unroll
    for (int j = 0; j < 16; j++) {
        float h0a, h0b, h1a, h1b;
        upk(h2a[j], h0a, h0b);
        upk(h2b[j], h1a, h1b);
        h0a = fmaxf(h0a, 0.0f); h0b = fmaxf(h0b, 0.0f);
        h1a = fmaxf(h1a, 0.0f); h1b = fmaxf(h1b, 0.0f);
        u64 xa0 = pk(h0a, h0a), xb0 = pk(h0b, h0b);
        u64 xa1 = pk(h1a, h1a), xb1 = pk(h1b, h1b);
        const ulonglong2* wra = (const ulonglong2*)&sw2[(2 * j) * 12];
        const ulonglong2* wrb = (const ulonglong2*)&sw2[(2 * j + 1) * 12];
#pragma unroll
        for (int q = 0; q < 6; q++) {
            ulonglong2 wpa = wra[q];
            ulonglong2 wpb = wrb[q];
            fma2(m2a[2 * q], wpa.x, xa0);
            fma2(m2a[2 * q + 1], wpa.y, xa0);
            fma2(m2a[2 * q], wpb.x, xb0);
            fma2(m2a[2 * q + 1], wpb.y, xb0);
            fma2(m2b[2 * q], wpa.x, xa1);
            fma2(m2b[2 * q + 1], wpa.y, xa1);
            fma2(m2b[2 * q], wpb.x, xb1);
            fma2(m2b[2 * q + 1], wpb.y, xb1);
        }
    }

    // ---- epilogue: edge outputs + m_b scatter (reload edge features; L1 hit) ----
    float ma0[D], ma1[D];
    {
        float m[MSG_OUT];
#pragma unroll
        for (int o = 0; o < 12; o++) upk(m2a[o], m[2 * o], m[2 * o + 1]);
#pragma unroll
        for (int c = 0; c < D; c++) ma0[c] = m[c];
        if (act0) {
            const float4* ep = (const float4*)(edges + ((size_t)b0 * E + e0) * CHE);
            float4 v0 = __ldg(ep + 0), v1 = __ldg(ep + 1);
            float4* op = (float4*)(new_edges + ((size_t)b0 * E + e0) * CHE);
            op[0] = make_float4(
                fminf(fmaxf(v0.x + m[16], -100.0f), 100.0f),
                fminf(fmaxf(v0.y + m[17], -100.0f), 100.0f),
                fminf(fmaxf(v0.z + m[18], -100.0f), 100.0f),
                fminf(fmaxf(v0.w + m[19], -100.0f), 100.0f));
            op[1] = make_float4(
                fminf(fmaxf(v1.x + m[20], -100.0f), 100.0f),
                fminf(fmaxf(v1.y + m[21], -100.0f), 100.0f),
                fminf(fmaxf(v1.z + m[22], -100.0f), 100.0f),
                fminf(fmaxf(v1.w + m[23], -100.0f), 100.0f));
            float* ab = g_agg_b + ((size_t)b0 * N + t0) * D;
            red4(ab,     m[8],  m[9],  m[10], m[11]);
            red4(ab + 4, m[12], m[13], m[14], m[15]);
        }
    }
    {
        float m[MSG_OUT];
#pragma unroll
        for (int o = 0; o < 12; o++) upk(m2b[o], m[2 * o], m[2 * o + 1]);
#pragma unroll
        for (int c = 0; c < D; c++) ma1[c] = m[c];
        if (act1) {
            const float4* ep = (const float4*)(edges + ((size_t)b1_ * E + e1) * CHE);
            float4 v0 = __ldg(ep + 0), v1 = __ldg(ep + 1);
            float4* op = (float4*)(new_edges + ((size_t)b1_ * E + e1) * CHE);
            op[0] = make_float4(
                fminf(fmaxf(v0.x + m[16], -100.0f), 100.0f),
                fminf(fmaxf(v0.y + m[17], -100.0f), 100.0f),
                fminf(fmaxf(v0.z + m[18], -100.0f), 100.0f),
                fminf(fmaxf(v0.w + m[19], -100.0f), 100.0f));
            op[1] = make_float4(
                fminf(fmaxf(v1.x + m[20], -100.0f), 100.0f),
                fminf(fmaxf(v1.y + m[21], -100.0f), 100.0f),
                fminf(fmaxf(v1.z + m[22], -100.0f), 100.0f),
                fminf(fmaxf(v1.w + m[23], -100.0f), 100.0f));
            float* ab = g_agg_b + ((size_t)b1_ * N + t1) * D;
            red4(ab,     m[8],  m[9],  m[10], m[11]);
            red4(ab + 4, m[12], m[13], m[14], m[15]);
        }
    }

    // ---- m_a scatter: combine pair when same source, then warp-uniform reduce ----
    const unsigned FULL = 0xffffffffu;
    float mc[D];
#pragma unroll
    for (int c = 0; c < D; c++) mc[c] = ma0[c] + (same_src ? ma1[c] : 0.0f);

    int su = __shfl_sync(FULL, s0, 0);
    int bu = __shfl_sync(FULL, b0, 0);
    bool uni = __all_sync(FULL, (s0 == su) && (b0 == bu)) && (su >= 0);
    if (uni) {
        float r[D];
#pragma unroll
        for (int c = 0; c < D; c++) {
            float v = mc[c];
#pragma unroll
            for (int off = 16; off; off >>= 1) v += __shfl_xor_sync(FULL, v, off);
            r[c] = v;
        }
        if (lane == 0) {
            float* aa = g_agg_a + ((size_t)bu * N + su) * D;
            red4(aa,     r[0], r[1], r[2], r[3]);
            red4(aa + 4, r[4], r[5], r[6], r[7]);
        }
        if (act1 && !same_src) {
            float* aa = g_agg_a + ((size_t)b1_ * N + s1) * D;
            red4(aa,     ma1[0], ma1[1], ma1[2], ma1[3]);
            red4(aa + 4, ma1[4], ma1[5], ma1[6], ma1[7]);
        }
    } else {
        if (act0) {
            float* aa = g_agg_a + ((size_t)b0 * N + s0) * D;
            red4(aa,     mc[0], mc[1], mc[2], mc[3]);
            red4(aa + 4, mc[4], mc[5], mc[6], mc[7]);
        }
        if (act1 && !same_src) {
            float* aa = g_agg_a + ((size_t)b1_ * N + s1) * D;
            red4(aa,     ma1[0], ma1[1], ma1[2], ma1[3]);
            red4(aa + 4, ma1[4], ma1[5], ma1[6], ma1[7]);
        }
    }
}

// ---------- kernel 3: per-node update MLP ----------
__global__ void k_node(const float* __restrict__ nodes,
                       const float* __restrict__ w1, const float* __restrict__ b1,
                       const float* __restrict__ w2, const float* __restrict__ b2,
                       float* __restrict__ new_nodes, int B, int N) {
    int idx = blockIdx.x * blockDim.x + threadIdx.x;
    if (idx >= B * N) return;
    int b = idx / N, n = idx - b * N;

    float ux[UPD_IN];
    float od = fmaxf(__ldg(&g_outdeg[n]), 1.0f);
    float idg = fmaxf(__ldg(&g_indeg[n]), 1.0f);
    const float* aa = g_agg_a + ((size_t)b * N + n) * D;
    const float* ab = g_agg_b + ((size_t)b * N + n) * D;
#pragma unroll
    for (int c = 0; c < D; c++) {
        ux[c] = aa[c] / od;
        ux[D + c] = ab[c] / idg;
    }
    const float* np = nodes + ((size_t)b * N + n) * CHN;
#pragma unroll
    for (int c = 0; c < CHN; c++) ux[2 * D + c] = __ldg(np + c);

    float uh[UPD_H];
#pragma unroll
    for (int j = 0; j < UPD_H; j++) {
        float acc = __ldg(&b1[j]);
#pragma unroll
        for (int f = 0; f < UPD_IN; f++) acc += __ldg(&w1[j * UPD_IN + f]) * ux[f];
        uh[j] = fmaxf(acc, 0.0f);
    }

    float* onp = new_nodes + ((size_t)b * N + n) * CHN;
#pragma unroll
    for (int o = 0; o < D; o++) {
        float acc = __ldg(&b2[o]);
#pragma unroll
        for (int j = 0; j < UPD_H; j++) acc += __ldg(&w2[o * UPD_H + j]) * uh[j];
        float v = ux[2 * D + o] + acc;
        onp[o] = fminf(fmaxf(v, -100.0f), 100.0f);
    }
#pragma unroll
    for (int c = D; c < CHN; c++) onp[c] = ux[2 * D + c];
}

extern "C" void kernel_launch(void* const* d_in, const int* in_sizes, int n_in,
                              void* d_out, int out_size) {
    const float* nodes  = (const float*)d_in[0];
    const float* edges  = (const float*)d_in[1];
    const float* msg_w1 = (const float*)d_in[2];
    const float* msg_b1 = (const float*)d_in[3];
    const float* msg_w2 = (const float*)d_in[4];
    const float* msg_b2 = (const float*)d_in[5];
    const float* upd_w1 = (const float*)d_in[6];
    const float* upd_b1 = (const float*)d_in[7];
    const float* upd_w2 = (const float*)d_in[8];
    const float* upd_b2 = (const float*)d_in[9];
    const int* src = (const int*)d_in[10];
    const int* tgt = (const int*)d_in[11];

    const int E = in_sizes[10];
    const int B = in_sizes[1] / (E * CHE);
    const int N = in_sizes[0] / (B * CHN);

    float* out_nodes = (float*)d_out;
    float* out_edges = out_nodes + (size_t)B * N * CHN;

    int zn = B * N * D;
    if (N > zn) zn = N;
    k_zero<<<(zn + 255) / 256, 256>>>(B, N);
    k_deg<<<(E + 255) / 256, 256>>>(src, tgt, E);
    k_pre<<<(B * N + 63) / 64, 64>>>(nodes, msg_w1, msg_b1, B, N);

    int tot = B * E;
    int blocks = (tot + 255) / 256;   // 256 edges per 128-thread block
    k_edge<<<blocks, 128>>>(edges, msg_w1, msg_w2, msg_b2,
                            src, tgt, out_edges, B, N, E);

    k_node<<<(B * N + 127) / 128, 128>>>(nodes, upd_w1, upd_b1, upd_w2, upd_b2,
                                         out_nodes, B, N);
    (void)n_in; (void)out_size;
}